// round 2
// baseline (speedup 1.0000x reference)
#include <cuda_runtime.h>

#define B     8
#define A     49104
#define C     20
#define M     32
#define NANN  16
#define AC    (A * C)            // 982080
#define IDX_PER_BLK 1024
#define NBLK  ((AC + IDX_PER_BLK - 1) / IDX_PER_BLK)   // 960
#define MAXLA 56

// ---- scratch (device globals; all slots written every call => no init kernel) ----
__device__ float g_part_cls[B][NBLK];
__device__ float g_part_reg[B][NBLK];
__device__ int   g_part_npos[B][NBLK];
__device__ int   g_count = 0;    // last block resets to 0 -> invariant across replays

__global__ void __launch_bounds__(256) k_fused(
    const float* __restrict__ cls_in,       // [B,A,C]
    const float* __restrict__ regressions,  // [B,A,4]
    const float* __restrict__ anchors,      // [1,A,4]
    const float* __restrict__ ema_in,       // [B,A,C]
    const float* __restrict__ ema_classes,  // [B,M]
    const float* __restrict__ ema_bboxes,   // [B,M,4]
    const int*   __restrict__ ema_counts,   // [B]
    const float* __restrict__ annotations,  // [B,N,5]
    float* __restrict__ out)
{
    __shared__ float sbx1[B][M], sby1[B][M], sbx2[B][M], sby2[B][M], sarea[B][M];
    __shared__ unsigned skeep[B];
    __shared__ unsigned char s_assigned[B][MAXLA];
    __shared__ float s_reg[B];
    __shared__ int   s_npos[B];
    __shared__ float s_wsum[B][8];
    __shared__ bool  s_last;

    const int tid  = threadIdx.x;
    const int blk  = blockIdx.x;
    const int lane = tid & 31;
    const int wrp  = tid >> 5;

    if (tid < B) { s_reg[tid] = 0.f; s_npos[tid] = 0; }

    // ---- load ema boxes + keep masks: warp b handles batch b ----
    {
        const int b = wrp, m = lane;
        const float* bb = ema_bboxes + (b * M + m) * 4;
        float x1 = bb[0], y1 = bb[1], x2 = bb[2], y2 = bb[3];
        sbx1[b][m] = x1; sby1[b][m] = y1; sbx2[b][m] = x2; sby2[b][m] = y2;
        sarea[b][m] = (x2 - x1) * (y2 - y1);
        bool valid = m < ema_counts[b];
        float cls = ema_classes[b * M + m];
        bool member = false;
        #pragma unroll
        for (int n = 0; n < NANN; n++)
            member |= (cls == annotations[(b * NANN + n) * 5 + 4]);
        unsigned mask = __ballot_sync(0xffffffffu, valid && member);
        if (m == 0) skeep[b] = mask;
    }
    __syncthreads();

    // ---- anchor range covered by this block's idx window ----
    const int idx0 = blk * IDX_PER_BLK;
    const int aLo  = idx0 / C;
    const int idxEnd = min(idx0 + IDX_PER_BLK - 1, AC - 1);
    const int aHi  = idxEnd / C;
    const int nA   = aHi - aLo + 1;   // <= 53

    // ---- assignment (recomputed locally): task = (la, b) ----
    for (int task = tid; task < nA * B; task += 256) {
        const int b  = task & 7;
        const int la = task >> 3;
        const int a  = aLo + la;

        float4 an = ((const float4*)anchors)[a];
        float aw = an.z - an.x, ah = an.w - an.y;
        float acx = an.x + 0.5f * aw, acy = an.y + 0.5f * ah;
        float area_a = aw * ah;

        unsigned km = skeep[b];
        float best = -1.f;
        int besti = 0;
        unsigned mm = km;
        // ascending m + strict '>' == jnp first-argmax; masked (-1) never wins
        while (mm) {
            int m = __ffs(mm) - 1;
            mm &= mm - 1;
            float iw = fminf(an.z, sbx2[b][m]) - fmaxf(an.x, sbx1[b][m]);
            float ih = fminf(an.w, sby2[b][m]) - fmaxf(an.y, sby1[b][m]);
            iw = fmaxf(iw, 0.f);
            ih = fmaxf(ih, 0.f);
            float inter = iw * ih;
            float ua = fmaxf(area_a + sarea[b][m] - inter, 1e-8f);
            float iou = inter / ua;
            if (iou > best) { best = iou; besti = m; }
        }
        bool has = (km != 0u);
        bool pos = has && (best >= 0.5f);
        bool assigned = has && ((best < 0.4f) || (best >= 0.5f));
        s_assigned[b][la] = assigned ? (unsigned char)1 : (unsigned char)0;

        // reg/npos owned by the block containing idx = a*C  (a*20/1024 == a*5>>8)
        if (pos && (((a * 5) >> 8) == blk)) {
            atomicAdd(&s_npos[b], 1);
            const float* r = regressions + ((size_t)b * A + a) * 4;
            float r0 = r[0], r1 = r[1], r2 = r[2], r3 = r[3];
            float bx1 = sbx1[b][besti], by1 = sby1[b][besti];
            float bx2 = sbx2[b][besti], by2 = sby2[b][besti];
            float gw = bx2 - bx1, gh = by2 - by1;
            float gcx = bx1 + 0.5f * gw, gcy = by1 + 0.5f * gh;
            gw = fmaxf(gw, 1.f);
            gh = fmaxf(gh, 1.f);
            float dx = (gcx - acx) / aw / 0.1f;
            float dy = (gcy - acy) / ah / 0.1f;
            float dw = __logf(gw / aw) / 0.2f;
            float dh = __logf(gh / ah) / 0.2f;
            float s = 0.f, d;
            d = fabsf(dx - r0); s += (d <= 1.f / 9.f) ? 4.5f * d * d : d - 0.5f / 9.f;
            d = fabsf(dy - r1); s += (d <= 1.f / 9.f) ? 4.5f * d * d : d - 0.5f / 9.f;
            d = fabsf(dw - r2); s += (d <= 1.f / 9.f) ? 4.5f * d * d : d - 0.5f / 9.f;
            d = fabsf(dh - r3); s += (d <= 1.f / 9.f) ? 4.5f * d * d : d - 0.5f / 9.f;
            atomicAdd(&s_reg[b], s);
        }
    }
    __syncthreads();

    // ---- classification consistency over this block's idx window ----
    float acc[B];
    #pragma unroll
    for (int b = 0; b < B; b++) acc[b] = 0.f;

    #pragma unroll
    for (int j = 0; j < 4; j++) {
        int idx = idx0 + j * 256 + tid;
        if (idx < AC) {
            int la = idx / C - aLo;
            float e[B];
            float S = 0.f;
            #pragma unroll
            for (int b = 0; b < B; b++) {
                e[b] = ema_in[(size_t)b * AC + idx];   // unclamped for alpha (bug-faithful)
                S += e[b];
            }
            float alpha = 0.4f + 0.9f * S;             // B*a0 + (a1-a0)*sum
            #pragma unroll
            for (int b = 0; b < B; b++) {
                if (s_assigned[b][la]) {
                    float ec = fminf(fmaxf(e[b], 1e-4f), 1.f - 1e-4f);
                    float c  = fminf(fmaxf(cls_in[(size_t)b * AC + idx], 1e-4f), 1.f - 1e-4f);
                    float bce = -(ec * __logf(c) + (1.f - ec) * __logf(1.f - c));
                    float d = ec - c;
                    acc[b] += alpha * (d * d) * bce;
                }
            }
        }
    }

    // deterministic per-block reduction: warp shuffle -> shared -> thread b
    #pragma unroll
    for (int b = 0; b < B; b++) {
        float v = acc[b];
        #pragma unroll
        for (int o = 16; o; o >>= 1) v += __shfl_down_sync(0xffffffffu, v, o);
        if (lane == 0) s_wsum[b][wrp] = v;
    }
    __syncthreads();
    if (tid < B) {
        float v = 0.f;
        #pragma unroll
        for (int w = 0; w < 8; w++) v += s_wsum[tid][w];
        g_part_cls[tid][blk]  = v;
        g_part_reg[tid][blk]  = s_reg[tid];
        g_part_npos[tid][blk] = s_npos[tid];
    }

    // ---- last-block final reduction ----
    __threadfence();
    __syncthreads();
    if (tid == 0) {
        int c = atomicAdd(&g_count, 1);
        s_last = (c == gridDim.x - 1);
    }
    __syncthreads();
    if (!s_last) return;
    __threadfence();

    // warp w reduces batch w over NBLK partials (coalesced: [b][i] layout)
    if (wrp < B) {
        const int b = wrp;
        float cs = 0.f, rs = 0.f;
        int   np = 0;
        for (int i = lane; i < NBLK; i += 32) {
            cs += g_part_cls[b][i];
            rs += g_part_reg[b][i];
            np += g_part_npos[b][i];
        }
        #pragma unroll
        for (int o = 16; o; o >>= 1) {
            cs += __shfl_down_sync(0xffffffffu, cs, o);
            rs += __shfl_down_sync(0xffffffffu, rs, o);
            np += __shfl_down_sync(0xffffffffu, np, o);
        }
        if (lane == 0) {
            float npf = (float)np;
            float mx  = fmaxf(npf, 1.f);
            s_wsum[0][b] = cs / mx;
            s_wsum[1][b] = (npf > 0.f) ? rs / (4.f * mx) : 0.f;
        }
    }
    __syncthreads();
    if (tid == 0) {
        float cs = 0.f, rs = 0.f;
        #pragma unroll
        for (int b = 0; b < B; b++) { cs += s_wsum[0][b]; rs += s_wsum[1][b]; }
        out[0] = cs * (1.f / (float)B);
        out[1] = rs * (1.f / (float)B);
        g_count = 0;   // restore invariant for next graph replay
    }
}

extern "C" void kernel_launch(void* const* d_in, const int* in_sizes, int n_in,
                              void* d_out, int out_size) {
    const float* classifications     = (const float*)d_in[0];
    const float* regressions         = (const float*)d_in[1];
    const float* anchors             = (const float*)d_in[2];
    const float* ema_classifications = (const float*)d_in[3];
    const float* ema_classes         = (const float*)d_in[4];
    const float* ema_bboxes          = (const float*)d_in[5];
    const int*   ema_counts          = (const int*)d_in[6];
    const float* annotations         = (const float*)d_in[7];

    k_fused<<<NBLK, 256>>>(classifications, regressions, anchors,
                           ema_classifications, ema_classes, ema_bboxes,
                           ema_counts, annotations, (float*)d_out);
}